// round 1
// baseline (speedup 1.0000x reference)
#include <cuda_runtime.h>
#include <cuda_bf16.h>

#define BB 16
#define HH 32
#define WW 32
#define CC 512
#define SS 1024            // H*W
#define HEADS 8
#define DHEAD 64
#define GROUPS 32
#define CPG 16             // C / GROUPS
#define NTOK (BB * SS)     // 16384

// ---------------- scratch (static device allocations; no cudaMalloc) --------
__device__ float g_xn [NTOK * CC];
__device__ float g_q  [NTOK * CC];
__device__ float g_k  [NTOK * CC];
__device__ float g_v  [NTOK * CC];
__device__ float g_att[NTOK * CC];

// ---------------- GroupNorm --------------------------------------------------
// grid = B*GROUPS blocks, 256 threads. Each block: one (b, g) group of
// 32*32*16 = 16384 elements.
__global__ __launch_bounds__(256) void gn_kernel(const float* __restrict__ x,
                                                 const float* __restrict__ gamma,
                                                 const float* __restrict__ beta) {
    const int b = blockIdx.x >> 5;
    const int g = blockIdx.x & 31;
    const float* xp = x + (size_t)b * SS * CC + g * CPG;

    float s = 0.f, s2 = 0.f;
    // 16384 elems = 4096 float4 loads (4 float4 per hw row of 16 ch)
    for (int i = threadIdx.x; i < 4096; i += 256) {
        int hw = i >> 2;
        int c4 = (i & 3) << 2;
        float4 v = *(const float4*)(xp + hw * CC + c4);
        s  += v.x + v.y + v.z + v.w;
        s2 += v.x * v.x + v.y * v.y + v.z * v.z + v.w * v.w;
    }
    // warp + block reduce
    for (int off = 16; off; off >>= 1) {
        s  += __shfl_down_sync(0xffffffffu, s,  off);
        s2 += __shfl_down_sync(0xffffffffu, s2, off);
    }
    __shared__ float ws[8], ws2[8], stat[2];
    int lane = threadIdx.x & 31, wid = threadIdx.x >> 5;
    if (lane == 0) { ws[wid] = s; ws2[wid] = s2; }
    __syncthreads();
    if (threadIdx.x == 0) {
        float ts = 0.f, ts2 = 0.f;
        for (int i = 0; i < 8; ++i) { ts += ws[i]; ts2 += ws2[i]; }
        float mean = ts * (1.f / 16384.f);
        float var  = ts2 * (1.f / 16384.f) - mean * mean;
        stat[0] = mean;
        stat[1] = rsqrtf(var + 1e-5f);
    }
    __syncthreads();
    const float mean = stat[0], rstd = stat[1];

    for (int i = threadIdx.x; i < 4096; i += 256) {
        int hw = i >> 2;
        int c4 = (i & 3) << 2;
        float4 v = *(const float4*)(xp + hw * CC + c4);
        int ch = g * CPG + c4;
        float4 o;
        o.x = (v.x - mean) * rstd * gamma[ch + 0] + beta[ch + 0];
        o.y = (v.y - mean) * rstd * gamma[ch + 1] + beta[ch + 1];
        o.z = (v.z - mean) * rstd * gamma[ch + 2] + beta[ch + 2];
        o.w = (v.w - mean) * rstd * gamma[ch + 3] + beta[ch + 3];
        *(float4*)(g_xn + (size_t)(b * SS + hw) * CC + ch) = o;
    }
}

// ---------------- QKV GEMM: [16384,512] @ [512,512] -> q/k/v (gridDim.z) ----
// 64x64 output tile, K-step 16, 256 threads, 4x4 micro-tile per thread.
__global__ __launch_bounds__(256) void qkv_gemm_kernel(const float* __restrict__ wq,
                                                       const float* __restrict__ wk,
                                                       const float* __restrict__ wv) {
    const float* W = (blockIdx.z == 0) ? wq : (blockIdx.z == 1) ? wk : wv;
    float* O = (blockIdx.z == 0) ? g_q : (blockIdx.z == 1) ? g_k : g_v;

    const int bm = blockIdx.y << 6;
    const int bn = blockIdx.x << 6;
    __shared__ float As[16][72];   // [k][m], padded so m-reads are 16B aligned
    __shared__ float Bs[16][64];   // [k][n]

    const int t = threadIdx.x;
    const int tm = (t >> 4) << 2;
    const int tn = (t & 15) << 2;
    const int arow = t >> 2, acol = (t & 3) << 2;   // A tile: 64 rows x 16 cols
    const int brow = t >> 4, bcol = (t & 15) << 2;  // B tile: 16 rows x 64 cols

    float acc[4][4] = {};
    const float* Arow = g_xn + (size_t)(bm + arow) * CC;

    for (int k0 = 0; k0 < CC; k0 += 16) {
        float4 av = *(const float4*)(Arow + k0 + acol);
        As[acol + 0][arow] = av.x;
        As[acol + 1][arow] = av.y;
        As[acol + 2][arow] = av.z;
        As[acol + 3][arow] = av.w;
        *(float4*)&Bs[brow][bcol] = *(const float4*)(W + (size_t)(k0 + brow) * CC + bn + bcol);
        __syncthreads();
#pragma unroll
        for (int kk = 0; kk < 16; ++kk) {
            float4 a = *(const float4*)&As[kk][tm];
            float4 bv = *(const float4*)&Bs[kk][tn];
            acc[0][0] += a.x * bv.x; acc[0][1] += a.x * bv.y; acc[0][2] += a.x * bv.z; acc[0][3] += a.x * bv.w;
            acc[1][0] += a.y * bv.x; acc[1][1] += a.y * bv.y; acc[1][2] += a.y * bv.z; acc[1][3] += a.y * bv.w;
            acc[2][0] += a.z * bv.x; acc[2][1] += a.z * bv.y; acc[2][2] += a.z * bv.z; acc[2][3] += a.z * bv.w;
            acc[3][0] += a.w * bv.x; acc[3][1] += a.w * bv.y; acc[3][2] += a.w * bv.z; acc[3][3] += a.w * bv.w;
        }
        __syncthreads();
    }
#pragma unroll
    for (int i = 0; i < 4; ++i) {
        float4 o = make_float4(acc[i][0], acc[i][1], acc[i][2], acc[i][3]);
        *(float4*)(O + (size_t)(bm + tm + i) * CC + bn + tn) = o;
    }
}

// ---------------- Attention (flash-style, 1 query row per thread) -----------
// grid.x = B*HEADS*4 = 512 blocks of 256 threads; each block: 256 queries of
// one (b, head). K/V streamed in 32-row smem tiles, online softmax.
__global__ __launch_bounds__(256) void attn_kernel() {
    const int bid = blockIdx.x;
    const int bh = bid >> 2;       // (b, head)
    const int qt = bid & 3;        // query quarter
    const int b = bh >> 3, h = bh & 7;

    const int qrow = b * SS + qt * 256 + threadIdx.x;
    const float* qp = g_q + (size_t)qrow * CC + h * DHEAD;

    float q[DHEAD];
#pragma unroll
    for (int d = 0; d < DHEAD; d += 4) {
        float4 v = *(const float4*)(qp + d);
        q[d + 0] = v.x * 0.125f;   // 1/sqrt(64) folded in
        q[d + 1] = v.y * 0.125f;
        q[d + 2] = v.z * 0.125f;
        q[d + 3] = v.w * 0.125f;
    }
    float o[DHEAD] = {};
    float m = -1e30f, l = 0.f;

    __shared__ float Ks[32][DHEAD];
    __shared__ float Vs[32][DHEAD];

    const int t = threadIdx.x;
    const int lrow = t >> 3;            // 0..31
    const int lcol = (t & 7) << 3;      // 0,8,...,56
    const size_t kbase = (size_t)(b * SS) * CC + h * DHEAD;

    for (int kt = 0; kt < SS / 32; ++kt) {
        const float* kp = g_k + kbase + (size_t)(kt * 32 + lrow) * CC + lcol;
        const float* vp = g_v + kbase + (size_t)(kt * 32 + lrow) * CC + lcol;
        *(float4*)&Ks[lrow][lcol]     = *(const float4*)(kp);
        *(float4*)&Ks[lrow][lcol + 4] = *(const float4*)(kp + 4);
        *(float4*)&Vs[lrow][lcol]     = *(const float4*)(vp);
        *(float4*)&Vs[lrow][lcol + 4] = *(const float4*)(vp + 4);
        __syncthreads();

        float sc[32];
        float mt = m;
#pragma unroll
        for (int kk = 0; kk < 32; ++kk) {
            float acc = 0.f;
#pragma unroll
            for (int d = 0; d < DHEAD; d += 4) {
                float4 kv = *(const float4*)&Ks[kk][d];
                acc += q[d] * kv.x + q[d + 1] * kv.y + q[d + 2] * kv.z + q[d + 3] * kv.w;
            }
            sc[kk] = acc;
            mt = fmaxf(mt, acc);
        }
        const float corr = __expf(m - mt);
        l *= corr;
#pragma unroll
        for (int d = 0; d < DHEAD; ++d) o[d] *= corr;
#pragma unroll
        for (int kk = 0; kk < 32; ++kk) {
            float p = __expf(sc[kk] - mt);
            l += p;
#pragma unroll
            for (int d = 0; d < DHEAD; d += 4) {
                float4 vv = *(const float4*)&Vs[kk][d];
                o[d + 0] += p * vv.x;
                o[d + 1] += p * vv.y;
                o[d + 2] += p * vv.z;
                o[d + 3] += p * vv.w;
            }
        }
        m = mt;
        __syncthreads();
    }

    const float inv = 1.f / l;
    float* op = g_att + (size_t)qrow * CC + h * DHEAD;
#pragma unroll
    for (int d = 0; d < DHEAD; d += 4) {
        float4 v = make_float4(o[d] * inv, o[d + 1] * inv, o[d + 2] * inv, o[d + 3] * inv);
        *(float4*)(op + d) = v;
    }
}

// ---------------- 3x3 conv (implicit GEMM) + bias + residual ----------------
// A = g_att [16384, 512] with per-tap spatial shift + boundary masking.
// 64x64 tile, K = 9 taps x 512, same micro-tile as the GEMM.
__global__ __launch_bounds__(256) void conv_kernel(const float* __restrict__ w,
                                                   const float* __restrict__ bias,
                                                   const float* __restrict__ x,
                                                   float* __restrict__ y) {
    const int bm = blockIdx.y << 6;
    const int bn = blockIdx.x << 6;
    __shared__ float As[16][72];
    __shared__ float Bs[16][64];

    const int t = threadIdx.x;
    const int tm = (t >> 4) << 2;
    const int tn = (t & 15) << 2;
    const int arow = t >> 2, acol = (t & 3) << 2;
    const int brow = t >> 4, bcol = (t & 15) << 2;

    // spatial position of this thread's A-tile row
    const int gm = bm + arow;
    const int b  = gm >> 10;
    const int s  = gm & 1023;
    const int pi = s >> 5, pj = s & 31;

    float acc[4][4] = {};

    for (int tap = 0; tap < 9; ++tap) {
        const int di = tap / 3 - 1, dj = tap % 3 - 1;
        const int ii = pi + di, jj = pj + dj;
        const bool valid = ((unsigned)ii < 32u) && ((unsigned)jj < 32u);
        const float* Arow = valid
            ? g_att + (size_t)((b << 10) + (ii << 5) + jj) * CC
            : nullptr;
        const float* Wtap = w + (size_t)tap * CC * CC;

        for (int k0 = 0; k0 < CC; k0 += 16) {
            float4 av = valid ? *(const float4*)(Arow + k0 + acol)
                              : make_float4(0.f, 0.f, 0.f, 0.f);
            As[acol + 0][arow] = av.x;
            As[acol + 1][arow] = av.y;
            As[acol + 2][arow] = av.z;
            As[acol + 3][arow] = av.w;
            *(float4*)&Bs[brow][bcol] =
                *(const float4*)(Wtap + (size_t)(k0 + brow) * CC + bn + bcol);
            __syncthreads();
#pragma unroll
            for (int kk = 0; kk < 16; ++kk) {
                float4 a  = *(const float4*)&As[kk][tm];
                float4 bv = *(const float4*)&Bs[kk][tn];
                acc[0][0] += a.x * bv.x; acc[0][1] += a.x * bv.y; acc[0][2] += a.x * bv.z; acc[0][3] += a.x * bv.w;
                acc[1][0] += a.y * bv.x; acc[1][1] += a.y * bv.y; acc[1][2] += a.y * bv.z; acc[1][3] += a.y * bv.w;
                acc[2][0] += a.z * bv.x; acc[2][1] += a.z * bv.y; acc[2][2] += a.z * bv.z; acc[2][3] += a.z * bv.w;
                acc[3][0] += a.w * bv.x; acc[3][1] += a.w * bv.y; acc[3][2] += a.w * bv.z; acc[3][3] += a.w * bv.w;
            }
            __syncthreads();
        }
    }
#pragma unroll
    for (int i = 0; i < 4; ++i) {
        const size_t row = (size_t)(bm + tm + i) * CC + bn + tn;
        float4 bi = *(const float4*)(bias + bn + tn);
        float4 xr = *(const float4*)(x + row);
        float4 o;
        o.x = acc[i][0] + bi.x + xr.x;
        o.y = acc[i][1] + bi.y + xr.y;
        o.z = acc[i][2] + bi.z + xr.z;
        o.w = acc[i][3] + bi.w + xr.w;
        *(float4*)(y + row) = o;
    }
}

// ---------------- launch -----------------------------------------------------
extern "C" void kernel_launch(void* const* d_in, const int* in_sizes, int n_in,
                              void* d_out, int out_size) {
    const float* x      = (const float*)d_in[0];
    const float* gamma  = (const float*)d_in[1];
    const float* beta   = (const float*)d_in[2];
    const float* wq     = (const float*)d_in[3];
    const float* wk     = (const float*)d_in[4];
    const float* wv     = (const float*)d_in[5];
    const float* conv_w = (const float*)d_in[6];
    const float* conv_b = (const float*)d_in[7];
    float* out = (float*)d_out;

    gn_kernel<<<BB * GROUPS, 256>>>(x, gamma, beta);

    dim3 ggrid(CC / 64, NTOK / 64, 3);
    qkv_gemm_kernel<<<ggrid, 256>>>(wq, wk, wv);

    attn_kernel<<<BB * HEADS * 4, 256>>>();

    dim3 cgrid(CC / 64, NTOK / 64);
    conv_kernel<<<cgrid, 256>>>(conv_w, conv_b, x, out);
}

// round 3
// speedup vs baseline: 1.6904x; 1.6904x over previous
#include <cuda_runtime.h>
#include <cuda_bf16.h>

#define BB 16
#define CC 512
#define SS 1024
#define HEADS 8
#define DHEAD 64
#define CPG 16
#define NTOK (BB * SS)

// ---------------- scratch ----------------------------------------------------
__device__ float g_xn [NTOK * CC];
__device__ float g_q  [NTOK * CC];
__device__ float g_k  [NTOK * CC];
__device__ float g_v  [NTOK * CC];
__device__ float g_att[NTOK * CC];

// ---------------- helpers ----------------------------------------------------
__device__ __forceinline__ unsigned f2tf32(float x) {
    unsigned r;
    asm("cvt.rna.tf32.f32 %0, %1;" : "=r"(r) : "f"(x));
    return r;
}

__device__ __forceinline__ void mma_tf32(float* c, const unsigned* a, const unsigned* b) {
    asm volatile(
        "mma.sync.aligned.m16n8k8.row.col.f32.tf32.tf32.f32 "
        "{%0,%1,%2,%3}, {%4,%5,%6,%7}, {%8,%9}, {%0,%1,%2,%3};\n"
        : "+f"(c[0]), "+f"(c[1]), "+f"(c[2]), "+f"(c[3])
        : "r"(a[0]), "r"(a[1]), "r"(a[2]), "r"(a[3]), "r"(b[0]), "r"(b[1]));
}

// smem pitches chosen for conflict-free fragment loads:
//  A pitch 36 floats: bank = (4*row + col) % 32 -> distinct over row 0..7, col 0..3
//  B pitch 136 floats: bank = (8*k + n) % 32   -> distinct over k 0..3, n 0..7
#define APITCH 36
#define BPITCH 136

// ---------------- GroupNorm --------------------------------------------------
__global__ __launch_bounds__(256) void gn_kernel(const float* __restrict__ x,
                                                 const float* __restrict__ gamma,
                                                 const float* __restrict__ beta) {
    const int b = blockIdx.x >> 5;
    const int g = blockIdx.x & 31;
    const float* xp = x + (size_t)b * SS * CC + g * CPG;

    float s = 0.f, s2 = 0.f;
    for (int i = threadIdx.x; i < 4096; i += 256) {
        int hw = i >> 2;
        int c4 = (i & 3) << 2;
        float4 v = *(const float4*)(xp + hw * CC + c4);
        s  += v.x + v.y + v.z + v.w;
        s2 += v.x * v.x + v.y * v.y + v.z * v.z + v.w * v.w;
    }
    for (int off = 16; off; off >>= 1) {
        s  += __shfl_down_sync(0xffffffffu, s,  off);
        s2 += __shfl_down_sync(0xffffffffu, s2, off);
    }
    __shared__ float ws[8], ws2[8], stat[2];
    int lane = threadIdx.x & 31, wid = threadIdx.x >> 5;
    if (lane == 0) { ws[wid] = s; ws2[wid] = s2; }
    __syncthreads();
    if (threadIdx.x == 0) {
        float ts = 0.f, ts2 = 0.f;
        for (int i = 0; i < 8; ++i) { ts += ws[i]; ts2 += ws2[i]; }
        float mean = ts * (1.f / 16384.f);
        float var  = ts2 * (1.f / 16384.f) - mean * mean;
        stat[0] = mean;
        stat[1] = rsqrtf(var + 1e-5f);
    }
    __syncthreads();
    const float mean = stat[0], rstd = stat[1];

    for (int i = threadIdx.x; i < 4096; i += 256) {
        int hw = i >> 2;
        int c4 = (i & 3) << 2;
        float4 v = *(const float4*)(xp + hw * CC + c4);
        int ch = g * CPG + c4;
        float4 o;
        o.x = (v.x - mean) * rstd * gamma[ch + 0] + beta[ch + 0];
        o.y = (v.y - mean) * rstd * gamma[ch + 1] + beta[ch + 1];
        o.z = (v.z - mean) * rstd * gamma[ch + 2] + beta[ch + 2];
        o.w = (v.w - mean) * rstd * gamma[ch + 3] + beta[ch + 3];
        *(float4*)(g_xn + (size_t)(b * SS + hw) * CC + ch) = o;
    }
}

// ---------------- QKV GEMM via tf32 HMMA -------------------------------------
// block tile 128x128, 8 warps (2x4), warp tile 64x32, K-chunk 32.
__global__ __launch_bounds__(256, 2) void qkv_gemm_kernel(const float* __restrict__ wq,
                                                          const float* __restrict__ wk,
                                                          const float* __restrict__ wv) {
    const float* W = (blockIdx.z == 0) ? wq : (blockIdx.z == 1) ? wk : wv;
    float* O = (blockIdx.z == 0) ? g_q : (blockIdx.z == 1) ? g_k : g_v;

    const int bm = blockIdx.y << 7;
    const int bn = blockIdx.x << 7;

    __shared__ unsigned A_s[128 * APITCH];
    __shared__ unsigned B_s[32 * BPITCH];

    const int t = threadIdx.x;
    const int wid = t >> 5, l = t & 31;
    const int g = l >> 2, tg = l & 3;
    const int warp_m = (wid >> 2) << 6;   // 0 or 64
    const int warp_n = (wid & 3) << 5;    // 0..96

    // staging coords
    const int ar = t >> 1, acb = (t & 1) << 4;     // A: row 0..127, col 0/16
    const int br = t >> 3, bcb = (t & 7) << 4;     // B: row 0..31,  col 0..112

    const float* Asrc = g_xn + (size_t)(bm + ar) * CC + acb;

    float acc[4][4][4] = {};

    for (int k0 = 0; k0 < CC; k0 += 32) {
#pragma unroll
        for (int i = 0; i < 4; ++i) {
            float4 v = *(const float4*)(Asrc + k0 + 4 * i);
            uint4 u = make_uint4(f2tf32(v.x), f2tf32(v.y), f2tf32(v.z), f2tf32(v.w));
            *(uint4*)&A_s[ar * APITCH + acb + 4 * i] = u;
        }
#pragma unroll
        for (int i = 0; i < 4; ++i) {
            float4 v = *(const float4*)(W + (size_t)(k0 + br) * CC + bn + bcb + 4 * i);
            uint4 u = make_uint4(f2tf32(v.x), f2tf32(v.y), f2tf32(v.z), f2tf32(v.w));
            *(uint4*)&B_s[br * BPITCH + bcb + 4 * i] = u;
        }
        __syncthreads();

#pragma unroll
        for (int ks = 0; ks < 4; ++ks) {
            unsigned a[4][4], bfr[4][2];
#pragma unroll
            for (int mt = 0; mt < 4; ++mt) {
                const int row = warp_m + (mt << 4);
                const int kc = (ks << 3) + tg;
                a[mt][0] = A_s[(row + g    ) * APITCH + kc    ];
                a[mt][1] = A_s[(row + g + 8) * APITCH + kc    ];
                a[mt][2] = A_s[(row + g    ) * APITCH + kc + 4];
                a[mt][3] = A_s[(row + g + 8) * APITCH + kc + 4];
            }
#pragma unroll
            for (int nt = 0; nt < 4; ++nt) {
                const int col = warp_n + (nt << 3) + g;
                const int kc = (ks << 3) + tg;
                bfr[nt][0] = B_s[(kc    ) * BPITCH + col];
                bfr[nt][1] = B_s[(kc + 4) * BPITCH + col];
            }
#pragma unroll
            for (int mt = 0; mt < 4; ++mt)
#pragma unroll
                for (int nt = 0; nt < 4; ++nt)
                    mma_tf32(acc[mt][nt], a[mt], bfr[nt]);
        }
        __syncthreads();
    }

#pragma unroll
    for (int mt = 0; mt < 4; ++mt) {
#pragma unroll
        for (int nt = 0; nt < 4; ++nt) {
            const int row = bm + warp_m + (mt << 4) + g;
            const int col = bn + warp_n + (nt << 3) + (tg << 1);
            *(float2*)(O + (size_t)row * CC + col) =
                make_float2(acc[mt][nt][0], acc[mt][nt][1]);
            *(float2*)(O + (size_t)(row + 8) * CC + col) =
                make_float2(acc[mt][nt][2], acc[mt][nt][3]);
        }
    }
}

// ---------------- Attention (flash-style, 1 query row per thread) -----------
__global__ __launch_bounds__(256) void attn_kernel() {
    const int bid = blockIdx.x;
    const int bh = bid >> 2;
    const int qt = bid & 3;
    const int b = bh >> 3, h = bh & 7;

    const int qrow = b * SS + qt * 256 + threadIdx.x;
    const float* qp = g_q + (size_t)qrow * CC + h * DHEAD;

    float q[DHEAD];
#pragma unroll
    for (int d = 0; d < DHEAD; d += 4) {
        float4 v = *(const float4*)(qp + d);
        q[d + 0] = v.x * 0.125f;
        q[d + 1] = v.y * 0.125f;
        q[d + 2] = v.z * 0.125f;
        q[d + 3] = v.w * 0.125f;
    }
    float o[DHEAD] = {};
    float m = -1e30f, l = 0.f;

    __shared__ float Ks[32][DHEAD];
    __shared__ float Vs[32][DHEAD];

    const int t = threadIdx.x;
    const int lrow = t >> 3;
    const int lcol = (t & 7) << 3;
    const size_t kbase = (size_t)(b * SS) * CC + h * DHEAD;

    for (int kt = 0; kt < SS / 32; ++kt) {
        const float* kp = g_k + kbase + (size_t)(kt * 32 + lrow) * CC + lcol;
        const float* vp = g_v + kbase + (size_t)(kt * 32 + lrow) * CC + lcol;
        *(float4*)&Ks[lrow][lcol]     = *(const float4*)(kp);
        *(float4*)&Ks[lrow][lcol + 4] = *(const float4*)(kp + 4);
        *(float4*)&Vs[lrow][lcol]     = *(const float4*)(vp);
        *(float4*)&Vs[lrow][lcol + 4] = *(const float4*)(vp + 4);
        __syncthreads();

        float sc[32];
        float mt = m;
#pragma unroll
        for (int kk = 0; kk < 32; ++kk) {
            float acc = 0.f;
#pragma unroll
            for (int d = 0; d < DHEAD; d += 4) {
                float4 kv = *(const float4*)&Ks[kk][d];
                acc += q[d] * kv.x + q[d + 1] * kv.y + q[d + 2] * kv.z + q[d + 3] * kv.w;
            }
            sc[kk] = acc;
            mt = fmaxf(mt, acc);
        }
        const float corr = __expf(m - mt);
        l *= corr;
#pragma unroll
        for (int d = 0; d < DHEAD; ++d) o[d] *= corr;
#pragma unroll
        for (int kk = 0; kk < 32; ++kk) {
            float p = __expf(sc[kk] - mt);
            l += p;
#pragma unroll
            for (int d = 0; d < DHEAD; d += 4) {
                float4 vv = *(const float4*)&Vs[kk][d];
                o[d + 0] += p * vv.x;
                o[d + 1] += p * vv.y;
                o[d + 2] += p * vv.z;
                o[d + 3] += p * vv.w;
            }
        }
        m = mt;
        __syncthreads();
    }

    const float inv = 1.f / l;
    float* op = g_att + (size_t)qrow * CC + h * DHEAD;
#pragma unroll
    for (int d = 0; d < DHEAD; d += 4) {
        float4 v = make_float4(o[d] * inv, o[d + 1] * inv, o[d + 2] * inv, o[d + 3] * inv);
        *(float4*)(op + d) = v;
    }
}

// ---------------- 3x3 conv (implicit GEMM) via tf32 HMMA --------------------
__global__ __launch_bounds__(256, 2) void conv_kernel(const float* __restrict__ w,
                                                      const float* __restrict__ bias,
                                                      const float* __restrict__ x,
                                                      float* __restrict__ y) {
    const int bm = blockIdx.y << 7;
    const int bn = blockIdx.x << 7;

    __shared__ unsigned A_s[128 * APITCH];
    __shared__ unsigned B_s[32 * BPITCH];

    const int t = threadIdx.x;
    const int wid = t >> 5, l = t & 31;
    const int g = l >> 2, tg = l & 3;
    const int warp_m = (wid >> 2) << 6;
    const int warp_n = (wid & 3) << 5;

    const int ar = t >> 1, acb = (t & 1) << 4;
    const int br = t >> 3, bcb = (t & 7) << 4;

    // spatial pos of this thread's staged A row
    const int token = bm + ar;
    const int b  = token >> 10;
    const int s  = token & 1023;
    const int pi = s >> 5, pj = s & 31;

    float acc[4][4][4] = {};

    for (int tap = 0; tap < 9; ++tap) {
        const int di = tap / 3 - 1, dj = tap % 3 - 1;
        const int ii = pi + di, jj = pj + dj;
        const bool valid = ((unsigned)ii < 32u) && ((unsigned)jj < 32u);
        const float* Asrc = valid
            ? g_att + (size_t)((b << 10) + (ii << 5) + jj) * CC + acb
            : nullptr;
        const float* Wtap = w + (size_t)tap * CC * CC;

        for (int k0 = 0; k0 < CC; k0 += 32) {
#pragma unroll
            for (int i = 0; i < 4; ++i) {
                float4 v = valid ? *(const float4*)(Asrc + k0 + 4 * i)
                                 : make_float4(0.f, 0.f, 0.f, 0.f);
                uint4 u = make_uint4(f2tf32(v.x), f2tf32(v.y), f2tf32(v.z), f2tf32(v.w));
                *(uint4*)&A_s[ar * APITCH + acb + 4 * i] = u;
            }
#pragma unroll
            for (int i = 0; i < 4; ++i) {
                float4 v = *(const float4*)(Wtap + (size_t)(k0 + br) * CC + bn + bcb + 4 * i);
                uint4 u = make_uint4(f2tf32(v.x), f2tf32(v.y), f2tf32(v.z), f2tf32(v.w));
                *(uint4*)&B_s[br * BPITCH + bcb + 4 * i] = u;
            }
            __syncthreads();

#pragma unroll
            for (int ks = 0; ks < 4; ++ks) {
                unsigned a[4][4], bfr[4][2];
#pragma unroll
                for (int mt = 0; mt < 4; ++mt) {
                    const int row = warp_m + (mt << 4);
                    const int kc = (ks << 3) + tg;
                    a[mt][0] = A_s[(row + g    ) * APITCH + kc    ];
                    a[mt][1] = A_s[(row + g + 8) * APITCH + kc    ];
                    a[mt][2] = A_s[(row + g    ) * APITCH + kc + 4];
                    a[mt][3] = A_s[(row + g + 8) * APITCH + kc + 4];
                }
#pragma unroll
                for (int nt = 0; nt < 4; ++nt) {
                    const int col = warp_n + (nt << 3) + g;
                    const int kc = (ks << 3) + tg;
                    bfr[nt][0] = B_s[(kc    ) * BPITCH + col];
                    bfr[nt][1] = B_s[(kc + 4) * BPITCH + col];
                }
#pragma unroll
                for (int mt = 0; mt < 4; ++mt)
#pragma unroll
                    for (int nt = 0; nt < 4; ++nt)
                        mma_tf32(acc[mt][nt], a[mt], bfr[nt]);
            }
            __syncthreads();
        }
    }

#pragma unroll
    for (int mt = 0; mt < 4; ++mt) {
#pragma unroll
        for (int nt = 0; nt < 4; ++nt) {
            const int row = bm + warp_m + (mt << 4) + g;
            const int col = bn + warp_n + (nt << 3) + (tg << 1);
            {
                const size_t off = (size_t)row * CC + col;
                float2 xr = *(const float2*)(x + off);
                float2 o;
                o.x = acc[mt][nt][0] + bias[col]     + xr.x;
                o.y = acc[mt][nt][1] + bias[col + 1] + xr.y;
                *(float2*)(y + off) = o;
            }
            {
                const size_t off = (size_t)(row + 8) * CC + col;
                float2 xr = *(const float2*)(x + off);
                float2 o;
                o.x = acc[mt][nt][2] + bias[col]     + xr.x;
                o.y = acc[mt][nt][3] + bias[col + 1] + xr.y;
                *(float2*)(y + off) = o;
            }
        }
    }
}

// ---------------- launch -----------------------------------------------------
extern "C" void kernel_launch(void* const* d_in, const int* in_sizes, int n_in,
                              void* d_out, int out_size) {
    const float* x      = (const float*)d_in[0];
    const float* gamma  = (const float*)d_in[1];
    const float* beta   = (const float*)d_in[2];
    const float* wq     = (const float*)d_in[3];
    const float* wk     = (const float*)d_in[4];
    const float* wv     = (const float*)d_in[5];
    const float* conv_w = (const float*)d_in[6];
    const float* conv_b = (const float*)d_in[7];
    float* out = (float*)d_out;

    gn_kernel<<<BB * 32, 256>>>(x, gamma, beta);

    dim3 ggrid(CC / 128, NTOK / 128, 3);
    qkv_gemm_kernel<<<ggrid, 256>>>(wq, wk, wv);

    attn_kernel<<<BB * HEADS * 4, 256>>>();

    dim3 cgrid(CC / 128, NTOK / 128);
    conv_kernel<<<cgrid, 256>>>(conv_w, conv_b, x, out);
}

// round 4
// speedup vs baseline: 5.0812x; 3.0059x over previous
#include <cuda_runtime.h>
#include <cuda_bf16.h>
#include <cstdint>

#define BB 16
#define CC 512
#define SS 1024
#define HEADS 8
#define DHEAD 64
#define NTOK (BB * SS)

typedef __nv_bfloat16 bf16;
typedef __nv_bfloat162 bf162;

// ---------------- scratch ----------------------------------------------------
__device__ bf16 g_xn [NTOK * CC];
__device__ bf16 g_q  [NTOK * CC];
__device__ bf16 g_k  [NTOK * CC];
__device__ bf16 g_v  [NTOK * CC];
__device__ bf16 g_att[NTOK * CC];
__device__ bf16 g_wt [12 * CC * CC];   // bf16, transposed [n][k]; 0-8 conv taps, 9-11 wq/wk/wv

// ---------------- PTX helpers -------------------------------------------------
__device__ __forceinline__ uint32_t s2u(const void* p) {
    return (uint32_t)__cvta_generic_to_shared(p);
}
__device__ __forceinline__ void cp16(uint32_t dst, const void* src, int sz) {
    asm volatile("cp.async.cg.shared.global [%0], [%1], 16, %2;" :: "r"(dst), "l"(src), "r"(sz));
}
__device__ __forceinline__ void cp_commit() { asm volatile("cp.async.commit_group;"); }
__device__ __forceinline__ void cp_wait0()  { asm volatile("cp.async.wait_group 0;"); }

__device__ __forceinline__ void ldsm4(uint32_t& r0, uint32_t& r1, uint32_t& r2, uint32_t& r3, uint32_t a) {
    asm volatile("ldmatrix.sync.aligned.m8n8.x4.shared.b16 {%0,%1,%2,%3}, [%4];"
                 : "=r"(r0), "=r"(r1), "=r"(r2), "=r"(r3) : "r"(a));
}
__device__ __forceinline__ void ldsm2(uint32_t& r0, uint32_t& r1, uint32_t a) {
    asm volatile("ldmatrix.sync.aligned.m8n8.x2.shared.b16 {%0,%1}, [%2];"
                 : "=r"(r0), "=r"(r1) : "r"(a));
}
__device__ __forceinline__ void ldsm2t(uint32_t& r0, uint32_t& r1, uint32_t a) {
    asm volatile("ldmatrix.sync.aligned.m8n8.x2.trans.shared.b16 {%0,%1}, [%2];"
                 : "=r"(r0), "=r"(r1) : "r"(a));
}
__device__ __forceinline__ void mma16816(float* c, const uint32_t* a, const uint32_t* b) {
    asm volatile("mma.sync.aligned.m16n8k16.row.col.f32.bf16.bf16.f32 "
                 "{%0,%1,%2,%3}, {%4,%5,%6,%7}, {%8,%9}, {%0,%1,%2,%3};"
                 : "+f"(c[0]), "+f"(c[1]), "+f"(c[2]), "+f"(c[3])
                 : "r"(a[0]), "r"(a[1]), "r"(a[2]), "r"(a[3]), "r"(b[0]), "r"(b[1]));
}
__device__ __forceinline__ uint32_t packbf(float lo, float hi) {
    bf162 v = __floats2bfloat162_rn(lo, hi);
    return *(uint32_t*)&v;
}

// smem pitch 40 bf16 (80B): ldmatrix phases (8 rows) land on distinct bank quads.
#define PITCH 40
// attention tile pitch 72 bf16 (144B): same property.
#define KPITCH 72

// ---------------- weight transpose + convert ---------------------------------
__global__ __launch_bounds__(256) void wcvt_kernel(const float* __restrict__ wq,
                                                   const float* __restrict__ wk,
                                                   const float* __restrict__ wv,
                                                   const float* __restrict__ cw) {
    const int z = blockIdx.z;
    const float* src = (z < 9) ? cw + (size_t)z * CC * CC
                               : (z == 9) ? wq : (z == 10) ? wk : wv;
    bf16* dst = g_wt + (size_t)z * CC * CC;
    __shared__ float tile[32][33];
    const int k0 = blockIdx.y << 5, n0 = blockIdx.x << 5;
    const int tx = threadIdx.x & 31, ty = threadIdx.x >> 5;
#pragma unroll
    for (int i = 0; i < 4; ++i)
        tile[ty + 8 * i][tx] = src[(size_t)(k0 + ty + 8 * i) * CC + n0 + tx];
    __syncthreads();
#pragma unroll
    for (int i = 0; i < 4; ++i)
        dst[(size_t)(n0 + ty + 8 * i) * CC + k0 + tx] = __float2bfloat16(tile[tx][ty + 8 * i]);
}

// ---------------- GroupNorm (f32 in -> bf16 out) -----------------------------
__global__ __launch_bounds__(256) void gn_kernel(const float* __restrict__ x,
                                                 const float* __restrict__ gamma,
                                                 const float* __restrict__ beta) {
    const int b = blockIdx.x >> 5;
    const int g = blockIdx.x & 31;
    const float* xp = x + (size_t)b * SS * CC + g * 16;

    float s = 0.f, s2 = 0.f;
    for (int i = threadIdx.x; i < 4096; i += 256) {
        int hw = i >> 2, c4 = (i & 3) << 2;
        float4 v = *(const float4*)(xp + hw * CC + c4);
        s  += v.x + v.y + v.z + v.w;
        s2 += v.x * v.x + v.y * v.y + v.z * v.z + v.w * v.w;
    }
    for (int off = 16; off; off >>= 1) {
        s  += __shfl_down_sync(0xffffffffu, s,  off);
        s2 += __shfl_down_sync(0xffffffffu, s2, off);
    }
    __shared__ float ws[8], ws2[8], stat[2];
    int lane = threadIdx.x & 31, wid = threadIdx.x >> 5;
    if (lane == 0) { ws[wid] = s; ws2[wid] = s2; }
    __syncthreads();
    if (threadIdx.x == 0) {
        float ts = 0.f, ts2 = 0.f;
        for (int i = 0; i < 8; ++i) { ts += ws[i]; ts2 += ws2[i]; }
        float mean = ts * (1.f / 16384.f);
        float var  = ts2 * (1.f / 16384.f) - mean * mean;
        stat[0] = mean; stat[1] = rsqrtf(var + 1e-5f);
    }
    __syncthreads();
    const float mean = stat[0], rstd = stat[1];

    for (int i = threadIdx.x; i < 4096; i += 256) {
        int hw = i >> 2, c4 = (i & 3) << 2;
        float4 v = *(const float4*)(xp + hw * CC + c4);
        int ch = g * 16 + c4;
        float o0 = (v.x - mean) * rstd * gamma[ch + 0] + beta[ch + 0];
        float o1 = (v.y - mean) * rstd * gamma[ch + 1] + beta[ch + 1];
        float o2 = (v.z - mean) * rstd * gamma[ch + 2] + beta[ch + 2];
        float o3 = (v.w - mean) * rstd * gamma[ch + 3] + beta[ch + 3];
        bf16* dp = g_xn + (size_t)(b * SS + hw) * CC + ch;
        *(bf162*)(dp)     = __floats2bfloat162_rn(o0, o1);
        *(bf162*)(dp + 2) = __floats2bfloat162_rn(o2, o3);
    }
}

// ---------------- QKV GEMM (bf16 HMMA, cp.async double buffer) ---------------
__global__ __launch_bounds__(256) void qkv_kernel() {
    const bf16* W = g_wt + (size_t)(9 + blockIdx.z) * CC * CC;   // [n][k] bf16
    bf16* O = (blockIdx.z == 0) ? g_q : (blockIdx.z == 1) ? g_k : g_v;
    const float scale = (blockIdx.z == 0) ? 0.125f : 1.0f;

    const int bm = blockIdx.y << 7, bn = blockIdx.x << 7;
    __shared__ __align__(16) bf16 As[2][128 * PITCH];
    __shared__ __align__(16) bf16 Bs[2][128 * PITCH];

    const int t = threadIdx.x;
    const int wid = t >> 5, l = t & 31, g = l >> 2, tg = l & 3;
    const int warp_m = (wid >> 2) << 6, warp_n = (wid & 3) << 5;

    const int srow = t & 127;
    const int sc0  = (t >> 7) << 1;
    const bf16* Ag = g_xn + (size_t)(bm + srow) * CC;
    const bf16* Bg = W    + (size_t)(bn + srow) * CC;
    const uint32_t a_sm0 = s2u(&As[0][srow * PITCH]);
    const uint32_t a_sm1 = s2u(&As[1][srow * PITCH]);
    const uint32_t b_sm0 = s2u(&Bs[0][srow * PITCH]);
    const uint32_t b_sm1 = s2u(&Bs[1][srow * PITCH]);

    float acc[4][4][4] = {};

    // prologue: chunk 0 -> stage 0
    {
        const int k0 = 0;
#pragma unroll
        for (int j = 0; j < 2; ++j) {
            cp16(a_sm0 + (sc0 + j) * 16, Ag + k0 + (sc0 + j) * 8, 16);
            cp16(b_sm0 + (sc0 + j) * 16, Bg + k0 + (sc0 + j) * 8, 16);
        }
        cp_commit();
    }

    for (int c = 0; c < 16; ++c) {
        cp_wait0();
        __syncthreads();
        if (c + 1 < 16) {
            const int k0 = (c + 1) << 5;
            const uint32_t a_sm = ((c + 1) & 1) ? a_sm1 : a_sm0;
            const uint32_t b_sm = ((c + 1) & 1) ? b_sm1 : b_sm0;
#pragma unroll
            for (int j = 0; j < 2; ++j) {
                cp16(a_sm + (sc0 + j) * 16, Ag + k0 + (sc0 + j) * 8, 16);
                cp16(b_sm + (sc0 + j) * 16, Bg + k0 + (sc0 + j) * 8, 16);
            }
            cp_commit();
        }
        const uint32_t ab = s2u(&As[c & 1][0]);
        const uint32_t bb = s2u(&Bs[c & 1][0]);
#pragma unroll
        for (int ks = 0; ks < 2; ++ks) {
            uint32_t a[4][4], bf[4][2];
#pragma unroll
            for (int mt = 0; mt < 4; ++mt) {
                const int row = warp_m + (mt << 4) + (l & 15);
                const int kc  = (ks << 4) + ((l >> 4) << 3);
                ldsm4(a[mt][0], a[mt][1], a[mt][2], a[mt][3], ab + (row * PITCH + kc) * 2);
            }
#pragma unroll
            for (int nt = 0; nt < 4; ++nt) {
                const int row = warp_n + (nt << 3) + (l & 7);
                const int kc  = (ks << 4) + (((l >> 3) & 1) << 3);
                ldsm2(bf[nt][0], bf[nt][1], bb + (row * PITCH + kc) * 2);
            }
#pragma unroll
            for (int mt = 0; mt < 4; ++mt)
#pragma unroll
                for (int nt = 0; nt < 4; ++nt)
                    mma16816(acc[mt][nt], a[mt], bf[nt]);
        }
        __syncthreads();
    }

#pragma unroll
    for (int mt = 0; mt < 4; ++mt)
#pragma unroll
        for (int nt = 0; nt < 4; ++nt) {
            const int r0 = bm + warp_m + (mt << 4) + g;
            const int col = bn + warp_n + (nt << 3) + (tg << 1);
            *(bf162*)(O + (size_t)r0 * CC + col) =
                __floats2bfloat162_rn(acc[mt][nt][0] * scale, acc[mt][nt][1] * scale);
            *(bf162*)(O + (size_t)(r0 + 8) * CC + col) =
                __floats2bfloat162_rn(acc[mt][nt][2] * scale, acc[mt][nt][3] * scale);
        }
}

// ---------------- Attention: FA2-style bf16 HMMA ------------------------------
// grid 1024: bid = bh*8 + qt. Block 256 thr = 8 warps, warp = 16 q rows.
__global__ __launch_bounds__(256) void attn_kernel() {
    const int bid = blockIdx.x;
    const int qt = bid & 7, bh = bid >> 3, b = bh >> 3, h = bh & 7;
    const int t = threadIdx.x, wid = t >> 5, l = t & 31, g = l >> 2, tg = l & 3;

    __shared__ __align__(16) bf16 Qs[128 * KPITCH];
    __shared__ __align__(16) bf16 Ks[64 * KPITCH];
    __shared__ __align__(16) bf16 Vs[64 * KPITCH];

    const int qrow0 = b * SS + qt * 128;

    // stage Q (128 rows x 128B)
    {
        const int r = t & 127, cb = (t >> 7) << 2;
        const bf16* src = g_q + (size_t)(qrow0 + r) * CC + h * DHEAD;
#pragma unroll
        for (int j = 0; j < 4; ++j)
            cp16(s2u(Qs) + (r * KPITCH + (cb + j) * 8) * 2, src + (cb + j) * 8, 16);
        cp_commit();
    }
    // stage K/V tile 0
    {
        const int r = t & 63, q4 = t >> 6;
        const bf16* base = (q4 < 2) ? g_k : g_v;
        bf16* dst = (q4 < 2) ? Ks : Vs;
        const int cb = (q4 & 1) << 2;
        const bf16* src = base + (size_t)(b * SS + r) * CC + h * DHEAD;
#pragma unroll
        for (int j = 0; j < 4; ++j)
            cp16(s2u(dst) + (r * KPITCH + (cb + j) * 8) * 2, src + (cb + j) * 8, 16);
        cp_commit();
    }
    cp_wait0();
    __syncthreads();

    // Q fragments to registers
    uint32_t qf[4][4];
    const int warp_q = wid << 4;
#pragma unroll
    for (int ks = 0; ks < 4; ++ks) {
        const int row = warp_q + (l & 15);
        const int kc  = (ks << 4) + ((l >> 4) << 3);
        ldsm4(qf[ks][0], qf[ks][1], qf[ks][2], qf[ks][3], s2u(Qs) + (row * KPITCH + kc) * 2);
    }

    float o[8][4] = {};
    float m0 = -1e30f, m1 = -1e30f, l0 = 0.f, l1 = 0.f;

    for (int kt = 0; kt < 16; ++kt) {
        // scores: 16 x 64
        float sc[8][4] = {};
#pragma unroll
        for (int ks = 0; ks < 4; ++ks) {
#pragma unroll
            for (int nt = 0; nt < 8; ++nt) {
                uint32_t kb[2];
                const int row = (nt << 3) + (l & 7);
                const int kc  = (ks << 4) + (((l >> 3) & 1) << 3);
                ldsm2(kb[0], kb[1], s2u(Ks) + (row * KPITCH + kc) * 2);
                mma16816(sc[nt], qf[ks], kb);
            }
        }
        // online softmax (rows g and g+8)
        float mr0 = m0, mr1 = m1;
#pragma unroll
        for (int nt = 0; nt < 8; ++nt) {
            mr0 = fmaxf(mr0, fmaxf(sc[nt][0], sc[nt][1]));
            mr1 = fmaxf(mr1, fmaxf(sc[nt][2], sc[nt][3]));
        }
        mr0 = fmaxf(mr0, __shfl_xor_sync(0xffffffffu, mr0, 1));
        mr0 = fmaxf(mr0, __shfl_xor_sync(0xffffffffu, mr0, 2));
        mr1 = fmaxf(mr1, __shfl_xor_sync(0xffffffffu, mr1, 1));
        mr1 = fmaxf(mr1, __shfl_xor_sync(0xffffffffu, mr1, 2));
        const float c0 = __expf(m0 - mr0), c1 = __expf(m1 - mr1);
        m0 = mr0; m1 = mr1;
        l0 *= c0; l1 *= c1;
#pragma unroll
        for (int nt = 0; nt < 8; ++nt) {
            o[nt][0] *= c0; o[nt][1] *= c0;
            o[nt][2] *= c1; o[nt][3] *= c1;
        }
        uint32_t pf[4][4];
#pragma unroll
        for (int ks = 0; ks < 4; ++ks) {
            const float p00 = __expf(sc[2*ks][0]   - m0), p01 = __expf(sc[2*ks][1]   - m0);
            const float p10 = __expf(sc[2*ks][2]   - m1), p11 = __expf(sc[2*ks][3]   - m1);
            const float p20 = __expf(sc[2*ks+1][0] - m0), p21 = __expf(sc[2*ks+1][1] - m0);
            const float p30 = __expf(sc[2*ks+1][2] - m1), p31 = __expf(sc[2*ks+1][3] - m1);
            l0 += p00 + p01 + p20 + p21;
            l1 += p10 + p11 + p30 + p31;
            pf[ks][0] = packbf(p00, p01);
            pf[ks][1] = packbf(p10, p11);
            pf[ks][2] = packbf(p20, p21);
            pf[ks][3] = packbf(p30, p31);
        }
        // PV: out += P @ V
#pragma unroll
        for (int ks = 0; ks < 4; ++ks) {
#pragma unroll
            for (int nt = 0; nt < 8; ++nt) {
                uint32_t vb[2];
                const int row = (ks << 4) + (l & 15);
                ldsm2t(vb[0], vb[1], s2u(Vs) + (row * KPITCH + (nt << 3)) * 2);
                mma16816(o[nt], pf[ks], vb);
            }
        }
        __syncthreads();   // done reading Ks/Vs
        if (kt + 1 < 16) {
            const int r = t & 63, q4 = t >> 6;
            const bf16* base = (q4 < 2) ? g_k : g_v;
            bf16* dst = (q4 < 2) ? Ks : Vs;
            const int cb = (q4 & 1) << 2;
            const bf16* src = base + (size_t)(b * SS + (kt + 1) * 64 + r) * CC + h * DHEAD;
#pragma unroll
            for (int j = 0; j < 4; ++j)
                cp16(s2u(dst) + (r * KPITCH + (cb + j) * 8) * 2, src + (cb + j) * 8, 16);
            cp_commit();
            cp_wait0();
        }
        __syncthreads();
    }

    float ls0 = l0 + __shfl_xor_sync(0xffffffffu, l0, 1);
    ls0 += __shfl_xor_sync(0xffffffffu, ls0, 2);
    float ls1 = l1 + __shfl_xor_sync(0xffffffffu, l1, 1);
    ls1 += __shfl_xor_sync(0xffffffffu, ls1, 2);
    const float inv0 = 1.f / ls0, inv1 = 1.f / ls1;

    const int r0 = qrow0 + warp_q + g;
#pragma unroll
    for (int nt = 0; nt < 8; ++nt) {
        const int col = h * DHEAD + (nt << 3) + (tg << 1);
        *(bf162*)(g_att + (size_t)r0 * CC + col) =
            __floats2bfloat162_rn(o[nt][0] * inv0, o[nt][1] * inv0);
        *(bf162*)(g_att + (size_t)(r0 + 8) * CC + col) =
            __floats2bfloat162_rn(o[nt][2] * inv1, o[nt][3] * inv1);
    }
}

// ---------------- 3x3 conv implicit GEMM (bf16 HMMA, double buffer) ----------
__global__ __launch_bounds__(256) void conv_kernel(const float* __restrict__ bias,
                                                   const float* __restrict__ x,
                                                   float* __restrict__ y) {
    const int bm = blockIdx.y << 7, bn = blockIdx.x << 7;
    __shared__ __align__(16) bf16 As[2][128 * PITCH];
    __shared__ __align__(16) bf16 Bs[2][128 * PITCH];

    const int t = threadIdx.x;
    const int wid = t >> 5, l = t & 31, g = l >> 2, tg = l & 3;
    const int warp_m = (wid >> 2) << 6, warp_n = (wid & 3) << 5;

    const int srow = t & 127;
    const int sc0  = (t >> 7) << 1;
    const int token = bm + srow;
    const int bi = token >> 10, s = token & 1023;
    const int pi = s >> 5, pj = s & 31;

    const uint32_t a_sm0 = s2u(&As[0][srow * PITCH]);
    const uint32_t a_sm1 = s2u(&As[1][srow * PITCH]);
    const uint32_t b_sm0 = s2u(&Bs[0][srow * PITCH]);
    const uint32_t b_sm1 = s2u(&Bs[1][srow * PITCH]);

    float acc[4][4][4] = {};

    // chunk c: tap = c>>4, k0 = (c&15)*32
#define CONV_STAGE(c, a_sm, b_sm) do {                                              \
        const int tap_ = (c) >> 4;                                                  \
        const int k0_ = ((c) & 15) << 5;                                            \
        const int di_ = (tap_ >= 6) ? 1 : (tap_ >= 3) ? 0 : -1;                     \
        const int dj_ = (tap_ % 3) - 1;                                             \
        const int ii_ = pi + di_, jj_ = pj + dj_;                                   \
        const bool v_ = ((unsigned)ii_ < 32u) && ((unsigned)jj_ < 32u);             \
        const bf16* Asrc_ = v_ ? g_att + (size_t)((bi << 10) + (ii_ << 5) + jj_) * CC \
                               : g_att;                                             \
        const bf16* Bsrc_ = g_wt + (size_t)tap_ * CC * CC + (size_t)(bn + srow) * CC; \
        const int az_ = v_ ? 16 : 0;                                                \
        _Pragma("unroll")                                                           \
        for (int j = 0; j < 2; ++j) {                                               \
            cp16((a_sm) + (sc0 + j) * 16, Asrc_ + k0_ + (sc0 + j) * 8, az_);        \
            cp16((b_sm) + (sc0 + j) * 16, Bsrc_ + k0_ + (sc0 + j) * 8, 16);         \
        }                                                                           \
        cp_commit();                                                                \
    } while (0)

    CONV_STAGE(0, a_sm0, b_sm0);

    for (int c = 0; c < 144; ++c) {
        cp_wait0();
        __syncthreads();
        if (c + 1 < 144) {
            if ((c + 1) & 1) CONV_STAGE(c + 1, a_sm1, b_sm1);
            else             CONV_STAGE(c + 1, a_sm0, b_sm0);
        }
        const uint32_t ab = s2u(&As[c & 1][0]);
        const uint32_t bb = s2u(&Bs[c & 1][0]);
#pragma unroll
        for (int ks = 0; ks < 2; ++ks) {
            uint32_t a[4][4], bf[4][2];
#pragma unroll
            for (int mt = 0; mt < 4; ++mt) {
                const int row = warp_m + (mt << 4) + (l & 15);
                const int kc  = (ks << 4) + ((l >> 4) << 3);
                ldsm4(a[mt][0], a[mt][1], a[mt][2], a[mt][3], ab + (row * PITCH + kc) * 2);
            }
#pragma unroll
            for (int nt = 0; nt < 4; ++nt) {
                const int row = warp_n + (nt << 3) + (l & 7);
                const int kc  = (ks << 4) + (((l >> 3) & 1) << 3);
                ldsm2(bf[nt][0], bf[nt][1], bb + (row * PITCH + kc) * 2);
            }
#pragma unroll
            for (int mt = 0; mt < 4; ++mt)
#pragma unroll
                for (int nt = 0; nt < 4; ++nt)
                    mma16816(acc[mt][nt], a[mt], bf[nt]);
        }
        __syncthreads();
    }
#undef CONV_STAGE

#pragma unroll
    for (int mt = 0; mt < 4; ++mt)
#pragma unroll
        for (int nt = 0; nt < 4; ++nt) {
            const int r0 = bm + warp_m + (mt << 4) + g;
            const int col = bn + warp_n + (nt << 3) + (tg << 1);
            {
                const size_t off = (size_t)r0 * CC + col;
                float2 xr = *(const float2*)(x + off);
                float2 ov;
                ov.x = acc[mt][nt][0] + bias[col]     + xr.x;
                ov.y = acc[mt][nt][1] + bias[col + 1] + xr.y;
                *(float2*)(y + off) = ov;
            }
            {
                const size_t off = (size_t)(r0 + 8) * CC + col;
                float2 xr = *(const float2*)(x + off);
                float2 ov;
                ov.x = acc[mt][nt][2] + bias[col]     + xr.x;
                ov.y = acc[mt][nt][3] + bias[col + 1] + xr.y;
                *(float2*)(y + off) = ov;
            }
        }
}

// ---------------- launch -----------------------------------------------------
extern "C" void kernel_launch(void* const* d_in, const int* in_sizes, int n_in,
                              void* d_out, int out_size) {
    const float* x      = (const float*)d_in[0];
    const float* gamma  = (const float*)d_in[1];
    const float* beta   = (const float*)d_in[2];
    const float* wq     = (const float*)d_in[3];
    const float* wk     = (const float*)d_in[4];
    const float* wv     = (const float*)d_in[5];
    const float* conv_w = (const float*)d_in[6];
    const float* conv_b = (const float*)d_in[7];
    float* out = (float*)d_out;

    dim3 wgrid(16, 16, 12);
    wcvt_kernel<<<wgrid, 256>>>(wq, wk, wv, conv_w);

    gn_kernel<<<BB * 32, 256>>>(x, gamma, beta);

    dim3 qgrid(CC / 128, NTOK / 128, 3);
    qkv_kernel<<<qgrid, 256>>>();

    attn_kernel<<<BB * HEADS * 8, 256>>>();

    dim3 cgrid(CC / 128, NTOK / 128);
    conv_kernel<<<cgrid, 256>>>(conv_b, x, out);
}

// round 15
// speedup vs baseline: 5.4670x; 1.0759x over previous
#include <cuda_runtime.h>
#include <cuda_bf16.h>
#include <cstdint>

#define BB 16
#define CC 512
#define SS 1024
#define HEADS 8
#define DHEAD 64
#define NTOK (BB * SS)

typedef __nv_bfloat16 bf16;
typedef __nv_bfloat162 bf162;

// ---------------- scratch ----------------------------------------------------
__device__ bf16 g_xn [NTOK * CC];
__device__ bf16 g_q  [NTOK * CC];
__device__ bf16 g_k  [NTOK * CC];
__device__ bf16 g_v  [NTOK * CC];
__device__ bf16 g_att[NTOK * CC];
__device__ bf16 g_wt [12 * CC * CC];   // bf16, transposed [n][k]; 0-8 conv taps, 9-11 wq/wk/wv

// ---------------- PTX helpers -------------------------------------------------
__device__ __forceinline__ uint32_t s2u(const void* p) {
    return (uint32_t)__cvta_generic_to_shared(p);
}
__device__ __forceinline__ void cp16(uint32_t dst, const void* src, int sz) {
    asm volatile("cp.async.cg.shared.global [%0], [%1], 16, %2;" :: "r"(dst), "l"(src), "r"(sz));
}
__device__ __forceinline__ void cp_commit() { asm volatile("cp.async.commit_group;"); }
__device__ __forceinline__ void cp_wait0()  { asm volatile("cp.async.wait_group 0;"); }
__device__ __forceinline__ void cp_wait1()  { asm volatile("cp.async.wait_group 1;"); }

__device__ __forceinline__ void ldsm4(uint32_t& r0, uint32_t& r1, uint32_t& r2, uint32_t& r3, uint32_t a) {
    asm volatile("ldmatrix.sync.aligned.m8n8.x4.shared.b16 {%0,%1,%2,%3}, [%4];"
                 : "=r"(r0), "=r"(r1), "=r"(r2), "=r"(r3) : "r"(a));
}
__device__ __forceinline__ void ldsm4t(uint32_t& r0, uint32_t& r1, uint32_t& r2, uint32_t& r3, uint32_t a) {
    asm volatile("ldmatrix.sync.aligned.m8n8.x4.trans.shared.b16 {%0,%1,%2,%3}, [%4];"
                 : "=r"(r0), "=r"(r1), "=r"(r2), "=r"(r3) : "r"(a));
}
__device__ __forceinline__ void mma16816(float* c, const uint32_t* a, const uint32_t* b) {
    asm volatile("mma.sync.aligned.m16n8k16.row.col.f32.bf16.bf16.f32 "
                 "{%0,%1,%2,%3}, {%4,%5,%6,%7}, {%8,%9}, {%0,%1,%2,%3};"
                 : "+f"(c[0]), "+f"(c[1]), "+f"(c[2]), "+f"(c[3])
                 : "r"(a[0]), "r"(a[1]), "r"(a[2]), "r"(a[3]), "r"(b[0]), "r"(b[1]));
}
__device__ __forceinline__ uint32_t packbf(float lo, float hi) {
    bf162 v = __floats2bfloat162_rn(lo, hi);
    return *(uint32_t*)&v;
}

#define PITCH 40     // GEMM stage pitch (80B rows -> conflict-free ldmatrix)
#define KPITCH 72    // attention tile pitch (144B rows -> conflict-free ldmatrix)

// ---------------- weight transpose + convert ---------------------------------
__global__ __launch_bounds__(256) void wcvt_kernel(const float* __restrict__ wq,
                                                   const float* __restrict__ wk,
                                                   const float* __restrict__ wv,
                                                   const float* __restrict__ cw) {
    const int z = blockIdx.z;
    const float* src = (z < 9) ? cw + (size_t)z * CC * CC
                               : (z == 9) ? wq : (z == 10) ? wk : wv;
    bf16* dst = g_wt + (size_t)z * CC * CC;
    __shared__ float tile[32][33];
    const int k0 = blockIdx.y << 5, n0 = blockIdx.x << 5;
    const int tx = threadIdx.x & 31, ty = threadIdx.x >> 5;
#pragma unroll
    for (int i = 0; i < 4; ++i)
        tile[ty + 8 * i][tx] = src[(size_t)(k0 + ty + 8 * i) * CC + n0 + tx];
    __syncthreads();
#pragma unroll
    for (int i = 0; i < 4; ++i)
        dst[(size_t)(n0 + ty + 8 * i) * CC + k0 + tx] = __float2bfloat16(tile[tx][ty + 8 * i]);
}

// ---------------- GroupNorm (f32 in -> bf16 out) -----------------------------
__global__ __launch_bounds__(256) void gn_kernel(const float* __restrict__ x,
                                                 const float* __restrict__ gamma,
                                                 const float* __restrict__ beta) {
    const int b = blockIdx.x >> 5;
    const int g = blockIdx.x & 31;
    const float* xp = x + (size_t)b * SS * CC + g * 16;

    float s = 0.f, s2 = 0.f;
    for (int i = threadIdx.x; i < 4096; i += 256) {
        int hw = i >> 2, c4 = (i & 3) << 2;
        float4 v = *(const float4*)(xp + hw * CC + c4);
        s  += v.x + v.y + v.z + v.w;
        s2 += v.x * v.x + v.y * v.y + v.z * v.z + v.w * v.w;
    }
    for (int off = 16; off; off >>= 1) {
        s  += __shfl_down_sync(0xffffffffu, s,  off);
        s2 += __shfl_down_sync(0xffffffffu, s2, off);
    }
    __shared__ float ws[8], ws2[8], stat[2];
    int lane = threadIdx.x & 31, wid = threadIdx.x >> 5;
    if (lane == 0) { ws[wid] = s; ws2[wid] = s2; }
    __syncthreads();
    if (threadIdx.x == 0) {
        float ts = 0.f, ts2 = 0.f;
        for (int i = 0; i < 8; ++i) { ts += ws[i]; ts2 += ws2[i]; }
        float mean = ts * (1.f / 16384.f);
        float var  = ts2 * (1.f / 16384.f) - mean * mean;
        stat[0] = mean; stat[1] = rsqrtf(var + 1e-5f);
    }
    __syncthreads();
    const float mean = stat[0], rstd = stat[1];

    for (int i = threadIdx.x; i < 4096; i += 256) {
        int hw = i >> 2, c4 = (i & 3) << 2;
        float4 v = *(const float4*)(xp + hw * CC + c4);
        int ch = g * 16 + c4;
        float o0 = (v.x - mean) * rstd * gamma[ch + 0] + beta[ch + 0];
        float o1 = (v.y - mean) * rstd * gamma[ch + 1] + beta[ch + 1];
        float o2 = (v.z - mean) * rstd * gamma[ch + 2] + beta[ch + 2];
        float o3 = (v.w - mean) * rstd * gamma[ch + 3] + beta[ch + 3];
        bf16* dp = g_xn + (size_t)(b * SS + hw) * CC + ch;
        *(bf162*)(dp)     = __floats2bfloat162_rn(o0, o1);
        *(bf162*)(dp + 2) = __floats2bfloat162_rn(o2, o3);
    }
}

// ---------------- shared GEMM compute step (on stage s) -----------------------
__device__ __forceinline__ void gemm_step(const bf16* As, const bf16* Bs,
                                          int warp_m, int warp_n, int l,
                                          float acc[4][4][4]) {
    const uint32_t ab = s2u(As);
    const uint32_t bb = s2u(Bs);
#pragma unroll
    for (int ks = 0; ks < 2; ++ks) {
        uint32_t a[4][4], bf[2][4];
#pragma unroll
        for (int mt = 0; mt < 4; ++mt) {
            const int row = warp_m + (mt << 4) + (l & 15);
            const int kc  = (ks << 4) + ((l >> 4) << 3);
            ldsm4(a[mt][0], a[mt][1], a[mt][2], a[mt][3], ab + (row * PITCH + kc) * 2);
        }
#pragma unroll
        for (int nt2 = 0; nt2 < 2; ++nt2) {
            const int row = warp_n + (nt2 << 4) + ((l >> 4) << 3) + (l & 7);
            const int kc  = (ks << 4) + (((l >> 3) & 1) << 3);
            ldsm4(bf[nt2][0], bf[nt2][1], bf[nt2][2], bf[nt2][3], bb + (row * PITCH + kc) * 2);
        }
#pragma unroll
        for (int mt = 0; mt < 4; ++mt)
#pragma unroll
            for (int nt2 = 0; nt2 < 2; ++nt2) {
                mma16816(acc[mt][2 * nt2],     a[mt], &bf[nt2][0]);
                mma16816(acc[mt][2 * nt2 + 1], a[mt], &bf[nt2][2]);
            }
    }
}

// ---------------- QKV GEMM (bf16 HMMA, 3-stage cp.async pipeline) ------------
__global__ __launch_bounds__(256) void qkv_kernel() {
    extern __shared__ __align__(16) bf16 dyn[];
    bf16* Ast = dyn;                       // 3 stages of 128*PITCH
    bf16* Bst = dyn + 3 * 128 * PITCH;

    const bf16* W = g_wt + (size_t)(9 + blockIdx.z) * CC * CC;
    bf16* O = (blockIdx.z == 0) ? g_q : (blockIdx.z == 1) ? g_k : g_v;
    const float scale = (blockIdx.z == 0) ? 0.125f : 1.0f;

    const int bm = blockIdx.y << 7, bn = blockIdx.x << 7;
    const int t = threadIdx.x;
    const int wid = t >> 5, l = t & 31, g = l >> 2, tg = l & 3;
    const int warp_m = (wid >> 2) << 6, warp_n = (wid & 3) << 5;

    const int srow = t & 127;
    const int sc0  = (t >> 7) << 1;
    const bf16* Ag = g_xn + (size_t)(bm + srow) * CC;
    const bf16* Bg = W    + (size_t)(bn + srow) * CC;

#define QKV_STAGE(c) do {                                                     \
        const int s_ = (c) % 3;                                               \
        const int k0_ = (c) << 5;                                             \
        const uint32_t asm_ = s2u(Ast + (s_ * 128 + srow) * PITCH);           \
        const uint32_t bsm_ = s2u(Bst + (s_ * 128 + srow) * PITCH);           \
        _Pragma("unroll")                                                     \
        for (int j = 0; j < 2; ++j) {                                         \
            cp16(asm_ + (sc0 + j) * 16, Ag + k0_ + (sc0 + j) * 8, 16);        \
            cp16(bsm_ + (sc0 + j) * 16, Bg + k0_ + (sc0 + j) * 8, 16);        \
        }                                                                     \
        cp_commit();                                                          \
    } while (0)

    float acc[4][4][4] = {};

    QKV_STAGE(0);
    QKV_STAGE(1);

    for (int c = 0; c < 16; ++c) {
        if (c + 1 < 16) cp_wait1(); else cp_wait0();
        __syncthreads();
        if (c + 2 < 16) QKV_STAGE(c + 2);
        gemm_step(Ast + (c % 3) * 128 * PITCH, Bst + (c % 3) * 128 * PITCH,
                  warp_m, warp_n, l, acc);
    }
#undef QKV_STAGE

#pragma unroll
    for (int mt = 0; mt < 4; ++mt)
#pragma unroll
        for (int nt = 0; nt < 4; ++nt) {
            const int r0 = bm + warp_m + (mt << 4) + g;
            const int col = bn + warp_n + (nt << 3) + (tg << 1);
            *(bf162*)(O + (size_t)r0 * CC + col) =
                __floats2bfloat162_rn(acc[mt][nt][0] * scale, acc[mt][nt][1] * scale);
            *(bf162*)(O + (size_t)(r0 + 8) * CC + col) =
                __floats2bfloat162_rn(acc[mt][nt][2] * scale, acc[mt][nt][3] * scale);
        }
}

// ---------------- Attention: FA2-style bf16 HMMA, double-buffered K/V --------
// Region A [0,128*KPITCH) holds Q then odd KV stages; region B holds even ones.
__global__ __launch_bounds__(256) void attn_kernel() {
    const int bid = blockIdx.x;
    const int qt = bid & 7, bh = bid >> 3, b = bh >> 3, h = bh & 7;
    const int t = threadIdx.x, wid = t >> 5, l = t & 31, g = l >> 2, tg = l & 3;

    __shared__ __align__(16) bf16 SM[2 * 128 * KPITCH];   // 36,864 B
    bf16* regA = SM;
    bf16* regB = SM + 128 * KPITCH;

    const int qrow0 = b * SS + qt * 128;

    // stage Q into region A
    {
        const int r = t & 127, cb = (t >> 7) << 2;
        const bf16* src = g_q + (size_t)(qrow0 + r) * CC + h * DHEAD;
#pragma unroll
        for (int j = 0; j < 4; ++j)
            cp16(s2u(regA) + (r * KPITCH + (cb + j) * 8) * 2, src + (cb + j) * 8, 16);
        cp_commit();
    }
    // stage K/V tile 0 into region B (K rows 0-63, V rows 64-127)
    const int svr = t & 63, svq = t >> 6;
    const int svcb = (svq & 1) << 2;
    {
        const bf16* base = (svq < 2) ? g_k : g_v;
        bf16* dst = regB + ((svq < 2) ? svr : 64 + svr) * KPITCH;
        const bf16* src = base + (size_t)(b * SS + svr) * CC + h * DHEAD;
#pragma unroll
        for (int j = 0; j < 4; ++j)
            cp16(s2u(dst) + ((svcb + j) * 8) * 2, src + (svcb + j) * 8, 16);
        cp_commit();
    }
    cp_wait0();
    __syncthreads();

    // Q fragments -> registers (region A becomes free after the kt=0 barrier)
    uint32_t qf[4][4];
    const int warp_q = wid << 4;
#pragma unroll
    for (int ks = 0; ks < 4; ++ks) {
        const int row = warp_q + (l & 15);
        const int kc  = (ks << 4) + ((l >> 4) << 3);
        ldsm4(qf[ks][0], qf[ks][1], qf[ks][2], qf[ks][3], s2u(regA) + (row * KPITCH + kc) * 2);
    }

    float o[8][4] = {};
    float m0 = -1e30f, m1 = -1e30f, l0 = 0.f, l1 = 0.f;

    for (int kt = 0; kt < 16; ++kt) {
        cp_wait0();
        __syncthreads();
        // prefetch next K/V tile BEFORE compute (into the other region)
        if (kt + 1 < 16) {
            bf16* reg = ((kt + 1) & 1) ? regA : regB;
            const bf16* base = (svq < 2) ? g_k : g_v;
            bf16* dst = reg + ((svq < 2) ? svr : 64 + svr) * KPITCH;
            const bf16* src = base + (size_t)(b * SS + (kt + 1) * 64 + svr) * CC + h * DHEAD;
#pragma unroll
            for (int j = 0; j < 4; ++j)
                cp16(s2u(dst) + ((svcb + j) * 8) * 2, src + (svcb + j) * 8, 16);
            cp_commit();
        }
        const bf16* reg = (kt & 1) ? regA : regB;
        const uint32_t kb_base = s2u(reg);               // K rows 0-63
        const uint32_t vb_base = s2u(reg + 64 * KPITCH); // V rows 0-63 (of V)

        // scores: 16 x 64
        float sc[8][4] = {};
#pragma unroll
        for (int ks = 0; ks < 4; ++ks) {
#pragma unroll
            for (int nt2 = 0; nt2 < 4; ++nt2) {
                uint32_t kb[4];
                const int row = (nt2 << 4) + ((l >> 4) << 3) + (l & 7);
                const int kc  = (ks << 4) + (((l >> 3) & 1) << 3);
                ldsm4(kb[0], kb[1], kb[2], kb[3], kb_base + (row * KPITCH + kc) * 2);
                mma16816(sc[2 * nt2],     qf[ks], &kb[0]);
                mma16816(sc[2 * nt2 + 1], qf[ks], &kb[2]);
            }
        }
        // online softmax (accumulator rows g and g+8)
        float mr0 = m0, mr1 = m1;
#pragma unroll
        for (int nt = 0; nt < 8; ++nt) {
            mr0 = fmaxf(mr0, fmaxf(sc[nt][0], sc[nt][1]));
            mr1 = fmaxf(mr1, fmaxf(sc[nt][2], sc[nt][3]));
        }
        mr0 = fmaxf(mr0, __shfl_xor_sync(0xffffffffu, mr0, 1));
        mr0 = fmaxf(mr0, __shfl_xor_sync(0xffffffffu, mr0, 2));
        mr1 = fmaxf(mr1, __shfl_xor_sync(0xffffffffu, mr1, 1));
        mr1 = fmaxf(mr1, __shfl_xor_sync(0xffffffffu, mr1, 2));
        const float c0 = __expf(m0 - mr0), c1 = __expf(m1 - mr1);
        m0 = mr0; m1 = mr1;
        l0 *= c0; l1 *= c1;
#pragma unroll
        for (int nt = 0; nt < 8; ++nt) {
            o[nt][0] *= c0; o[nt][1] *= c0;
            o[nt][2] *= c1; o[nt][3] *= c1;
        }
        uint32_t pf[4][4];
#pragma unroll
        for (int ks = 0; ks < 4; ++ks) {
            const float p00 = __expf(sc[2*ks][0]   - m0), p01 = __expf(sc[2*ks][1]   - m0);
            const float p10 = __expf(sc[2*ks][2]   - m1), p11 = __expf(sc[2*ks][3]   - m1);
            const float p20 = __expf(sc[2*ks+1][0] - m0), p21 = __expf(sc[2*ks+1][1] - m0);
            const float p30 = __expf(sc[2*ks+1][2] - m1), p31 = __expf(sc[2*ks+1][3] - m1);
            l0 += p00 + p01 + p20 + p21;
            l1 += p10 + p11 + p30 + p31;
            pf[ks][0] = packbf(p00, p01);
            pf[ks][1] = packbf(p10, p11);
            pf[ks][2] = packbf(p20, p21);
            pf[ks][3] = packbf(p30, p31);
        }
        // PV: out += P @ V  (V fragments via ldsm4 trans, two d-tiles each)
#pragma unroll
        for (int ks = 0; ks < 4; ++ks) {
#pragma unroll
            for (int nt2 = 0; nt2 < 4; ++nt2) {
                uint32_t vb[4];
                const int row = (ks << 4) + (l & 15);
                const int col = (nt2 << 4) + ((l >> 4) << 3);
                ldsm4t(vb[0], vb[1], vb[2], vb[3], vb_base + (row * KPITCH + col) * 2);
                mma16816(o[2 * nt2],     pf[ks], &vb[0]);
                mma16816(o[2 * nt2 + 1], pf[ks], &vb[2]);
            }
        }
    }

    float ls0 = l0 + __shfl_xor_sync(0xffffffffu, l0, 1);
    ls0 += __shfl_xor_sync(0xffffffffu, ls0, 2);
    float ls1 = l1 + __shfl_xor_sync(0xffffffffu, l1, 1);
    ls1 += __shfl_xor_sync(0xffffffffu, ls1, 2);
    const float inv0 = 1.f / ls0, inv1 = 1.f / ls1;

    const int r0 = qrow0 + warp_q + g;
#pragma unroll
    for (int nt = 0; nt < 8; ++nt) {
        const int col = h * DHEAD + (nt << 3) + (tg << 1);
        *(bf162*)(g_att + (size_t)r0 * CC + col) =
            __floats2bfloat162_rn(o[nt][0] * inv0, o[nt][1] * inv0);
        *(bf162*)(g_att + (size_t)(r0 + 8) * CC + col) =
            __floats2bfloat162_rn(o[nt][2] * inv1, o[nt][3] * inv1);
    }
}

// ---------------- 3x3 conv implicit GEMM (bf16 HMMA, 3-stage pipeline) -------
__global__ __launch_bounds__(256) void conv_kernel(const float* __restrict__ bias,
                                                   const float* __restrict__ x,
                                                   float* __restrict__ y) {
    extern __shared__ __align__(16) bf16 dyn[];
    bf16* Ast = dyn;
    bf16* Bst = dyn + 3 * 128 * PITCH;

    const int bm = blockIdx.y << 7, bn = blockIdx.x << 7;
    const int t = threadIdx.x;
    const int wid = t >> 5, l = t & 31, g = l >> 2, tg = l & 3;
    const int warp_m = (wid >> 2) << 6, warp_n = (wid & 3) << 5;

    const int srow = t & 127;
    const int sc0  = (t >> 7) << 1;
    const int token = bm + srow;
    const int bi = token >> 10, s = token & 1023;
    const int pi = s >> 5, pj = s & 31;

#define CONV_STAGE(c) do {                                                          \
        const int s_ = (c) % 3;                                                     \
        const int tap_ = (c) >> 4;                                                  \
        const int k0_ = ((c) & 15) << 5;                                            \
        const int di_ = (tap_ >= 6) ? 1 : (tap_ >= 3) ? 0 : -1;                     \
        const int dj_ = (tap_ % 3) - 1;                                             \
        const int ii_ = pi + di_, jj_ = pj + dj_;                                   \
        const bool v_ = ((unsigned)ii_ < 32u) && ((unsigned)jj_ < 32u);             \
        const bf16* Asrc_ = v_ ? g_att + (size_t)((bi << 10) + (ii_ << 5) + jj_) * CC \
                               : g_att;                                             \
        const bf16* Bsrc_ = g_wt + (size_t)tap_ * CC * CC + (size_t)(bn + srow) * CC; \
        const int az_ = v_ ? 16 : 0;                                                \
        const uint32_t asm_ = s2u(Ast + (s_ * 128 + srow) * PITCH);                 \
        const uint32_t bsm_ = s2u(Bst + (s_ * 128 + srow) * PITCH);                 \
        _Pragma("unroll")                                                           \
        for (int j = 0; j < 2; ++j) {                                               \
            cp16(asm_ + (sc0 + j) * 16, Asrc_ + k0_ + (sc0 + j) * 8, az_);          \
            cp16(bsm_ + (sc0 + j) * 16, Bsrc_ + k0_ + (sc0 + j) * 8, 16);           \
        }                                                                           \
        cp_commit();                                                                \
    } while (0)

    float acc[4][4][4] = {};

    CONV_STAGE(0);
    CONV_STAGE(1);

    for (int c = 0; c < 144; ++c) {
        if (c + 1 < 144) cp_wait1(); else cp_wait0();
        __syncthreads();
        if (c + 2 < 144) CONV_STAGE(c + 2);
        gemm_step(Ast + (c % 3) * 128 * PITCH, Bst + (c % 3) * 128 * PITCH,
                  warp_m, warp_n, l, acc);
    }
#undef CONV_STAGE

#pragma unroll
    for (int mt = 0; mt < 4; ++mt)
#pragma unroll
        for (int nt = 0; nt < 4; ++nt) {
            const int r0 = bm + warp_m + (mt << 4) + g;
            const int col = bn + warp_n + (nt << 3) + (tg << 1);
            {
                const size_t off = (size_t)r0 * CC + col;
                float2 xr = *(const float2*)(x + off);
                float2 ov;
                ov.x = acc[mt][nt][0] + bias[col]     + xr.x;
                ov.y = acc[mt][nt][1] + bias[col + 1] + xr.y;
                *(float2*)(y + off) = ov;
            }
            {
                const size_t off = (size_t)(r0 + 8) * CC + col;
                float2 xr = *(const float2*)(x + off);
                float2 ov;
                ov.x = acc[mt][nt][2] + bias[col]     + xr.x;
                ov.y = acc[mt][nt][3] + bias[col + 1] + xr.y;
                *(float2*)(y + off) = ov;
            }
        }
}

// ---------------- launch -----------------------------------------------------
extern "C" void kernel_launch(void* const* d_in, const int* in_sizes, int n_in,
                              void* d_out, int out_size) {
    const float* x      = (const float*)d_in[0];
    const float* gamma  = (const float*)d_in[1];
    const float* beta   = (const float*)d_in[2];
    const float* wq     = (const float*)d_in[3];
    const float* wk     = (const float*)d_in[4];
    const float* wv     = (const float*)d_in[5];
    const float* conv_w = (const float*)d_in[6];
    const float* conv_b = (const float*)d_in[7];
    float* out = (float*)d_out;

    const int gemm_smem = 6 * 128 * PITCH * sizeof(bf16);   // 61,440 B
    cudaFuncSetAttribute(qkv_kernel,  cudaFuncAttributeMaxDynamicSharedMemorySize, gemm_smem);
    cudaFuncSetAttribute(conv_kernel, cudaFuncAttributeMaxDynamicSharedMemorySize, gemm_smem);

    dim3 wgrid(16, 16, 12);
    wcvt_kernel<<<wgrid, 256>>>(wq, wk, wv, conv_w);

    gn_kernel<<<BB * 32, 256>>>(x, gamma, beta);

    dim3 qgrid(CC / 128, NTOK / 128, 3);
    qkv_kernel<<<qgrid, 256, gemm_smem>>>();

    attn_kernel<<<BB * HEADS * 8, 256>>>();

    dim3 cgrid(CC / 128, NTOK / 128);
    conv_kernel<<<cgrid, 256, gemm_smem>>>(conv_b, x, out);
}